// round 1
// baseline (speedup 1.0000x reference)
#include <cuda_runtime.h>

#define D 32
#define EPSF      1e-6f
#define MIN_NORM  1e-15f
#define MAX_NORM  (1.0f - 1e-5f)

// Persistent device state (no allocations allowed)
__device__ double g_acc[33];   // [0..31] vector accumulator, [32] scalar accumulator
__device__ float  g_mu[D];
__device__ float  g_mu2;
__device__ float  g_onm[D];
__device__ float  g_onm2;
__device__ float  g_factor;

__device__ __forceinline__ float warp_sum(float v) {
#pragma unroll
    for (int o = 16; o > 0; o >>= 1)
        v += __shfl_xor_sync(0xffffffffu, v, o);
    return v;
}

// ---------------------------------------------------------------------------
// zero accumulators
__global__ void k_zero() {
    int t = threadIdx.x;
    if (t < 33) g_acc[t] = 0.0;
}

// ---------------------------------------------------------------------------
// Pass 1: sum of log0(x) over rows
__global__ void __launch_bounds__(256) k_pass_log0(const float* __restrict__ x, int N) {
    __shared__ float smem[D];
    int tid  = threadIdx.x;
    int lane = tid & 31;
    int warp = tid >> 5;
    if (tid < D) smem[tid] = 0.0f;
    __syncthreads();

    const int wpb = blockDim.x >> 5;
    long long row    = (long long)blockIdx.x * wpb + warp;
    long long stride = (long long)gridDim.x * wpb;

    float acc = 0.0f;
    for (; row < N; row += stride) {
        float xi = x[row * D + lane];
        float n  = sqrtf(warp_sum(xi * xi));
        float nc = fminf(fmaxf(n, MIN_NORM), MAX_NORM);
        acc += atanhf(nc) * (xi / nc);
    }
    atomicAdd(&smem[lane], acc);
    __syncthreads();
    if (tid < D) atomicAdd(&g_acc[tid], (double)smem[tid]);
}

// mu = exp0(acc / N); zero acc
__global__ void k_fin_exp0(int N) {
    int l = threadIdx.x;               // 32 threads
    float v  = (float)(g_acc[l] / (double)N);
    float n  = fmaxf(sqrtf(warp_sum(v * v)), MIN_NORM);
    float mu = tanhf(n) * (v / n);
    g_mu[l]  = mu;
    float m2 = warp_sum(mu * mu);
    g_acc[l] = 0.0;
    if (l == 0) { g_mu2 = m2; g_acc[32] = 0.0; }
}

// ---------------------------------------------------------------------------
// Frechet iteration pass: sum of log_map(mu, x) over rows
__global__ void __launch_bounds__(256) k_pass_logmap(const float* __restrict__ x, int N) {
    __shared__ float smem[D];
    int tid  = threadIdx.x;
    int lane = tid & 31;
    int warp = tid >> 5;
    if (tid < D) smem[tid] = 0.0f;
    __syncthreads();

    const float mu_l  = g_mu[lane];
    const float mu2   = g_mu2;
    const float omm2  = 1.0f - mu2;   // (1 - |mu|^2)

    const int wpb = blockDim.x >> 5;
    long long row    = (long long)blockIdx.x * wpb + warp;
    long long stride = (long long)gridDim.x * wpb;

    float acc = 0.0f;
    for (; row < N; row += stride) {
        float y  = x[row * D + lane];
        // mobius_add(-mu, y)
        float xy = warp_sum(-mu_l * y);
        float y2 = warp_sum(y * y);
        float a  = 1.0f + 2.0f * xy;
        float num = (a + y2) * (-mu_l) + omm2 * y;
        float den = fmaxf(a + mu2 * y2, MIN_NORM);
        float w   = num / den;
        float n   = sqrtf(warp_sum(w * w));
        float nc  = fminf(fmaxf(n, MIN_NORM), MAX_NORM);
        acc += omm2 * atanhf(nc) * (w / nc);
    }
    atomicAdd(&smem[lane], acc);
    __syncthreads();
    if (tid < D) atomicAdd(&g_acc[tid], (double)smem[tid]);
}

// mu = exp_map(mu, acc / N); zero acc
__global__ void k_fin_iter(int N) {
    int l = threadIdx.x;               // 32 threads
    float v   = (float)(g_acc[l] / (double)N);
    float mu  = g_mu[l];
    float mu2 = g_mu2;

    float n = fmaxf(sqrtf(warp_sum(v * v)), MIN_NORM);
    float u = tanhf(n / (1.0f - mu2)) * (v / n);

    // mobius_add(mu, u)
    float xy = warp_sum(mu * u);
    float u2 = warp_sum(u * u);
    float a  = 1.0f + 2.0f * xy;
    float num = (a + u2) * mu + (1.0f - mu2) * u;
    float den = fmaxf(a + mu2 * u2, MIN_NORM);
    float mun = num / den;

    g_mu[l]  = mun;
    float m2 = warp_sum(mun * mun);
    g_acc[l] = 0.0;
    if (l == 0) { g_mu2 = m2; g_acc[32] = 0.0; }
}

// ---------------------------------------------------------------------------
// Variance pass: sum of (2*atanh(|mobius_add(-mu,x)|))^2
__global__ void __launch_bounds__(256) k_pass_var(const float* __restrict__ x, int N) {
    __shared__ float ssum;
    int tid  = threadIdx.x;
    int lane = tid & 31;
    int warp = tid >> 5;
    if (tid == 0) ssum = 0.0f;
    __syncthreads();

    const float mu_l = g_mu[lane];
    const float mu2  = g_mu2;
    const float omm2 = 1.0f - mu2;

    const int wpb = blockDim.x >> 5;
    long long row    = (long long)blockIdx.x * wpb + warp;
    long long stride = (long long)gridDim.x * wpb;

    float acc = 0.0f;
    for (; row < N; row += stride) {
        float y  = x[row * D + lane];
        float xy = warp_sum(-mu_l * y);
        float y2 = warp_sum(y * y);
        float a  = 1.0f + 2.0f * xy;
        float num = (a + y2) * (-mu_l) + omm2 * y;
        float den = fmaxf(a + mu2 * y2, MIN_NORM);
        float w   = num / den;
        float n   = sqrtf(warp_sum(w * w));
        float nc  = fminf(fmaxf(n, 0.0f), MAX_NORM);
        float d   = 2.0f * atanhf(nc);
        if (lane == 0) acc += d * d;
    }
    if (lane == 0) atomicAdd(&ssum, acc);
    __syncthreads();
    if (tid == 0) atomicAdd(&g_acc[32], (double)ssum);
}

// factor, on_manifold; also write input_mean to the output tail
__global__ void k_fin_var(const float* __restrict__ var_param,
                          const float* __restrict__ mean_param,
                          float* __restrict__ out, int N) {
    int l = threadIdx.x;               // 32 threads
    float var    = (float)(g_acc[32] / (double)N);
    float factor = var_param[0] / sqrtf(var + EPSF);

    float m   = mean_param[l];
    float n   = fmaxf(sqrtf(warp_sum(m * m)), MIN_NORM);
    float onm = tanhf(n) * (m / n);
    g_onm[l]  = onm;
    float o2  = warp_sum(onm * onm);
    if (l == 0) { g_onm2 = o2; g_factor = factor; g_acc[32] = 0.0; }

    // input_mean appended after the N*D normalized outputs
    out[(long long)N * D + l] = g_mu[l];
}

// ---------------------------------------------------------------------------
// Final transform: out = mobius_add(onm, mobius_scalar_mul(factor, mobius_add(-mu, x)))
__global__ void __launch_bounds__(256) k_pass_transform(const float* __restrict__ x,
                                                        float* __restrict__ out, int N) {
    int tid  = threadIdx.x;
    int lane = tid & 31;
    int warp = tid >> 5;

    const float mu_l   = g_mu[lane];
    const float mu2    = g_mu2;
    const float omm2   = 1.0f - mu2;
    const float onm_l  = g_onm[lane];
    const float onm2   = g_onm2;
    const float factor = g_factor;

    const int wpb = blockDim.x >> 5;
    long long row    = (long long)blockIdx.x * wpb + warp;
    long long stride = (long long)gridDim.x * wpb;

    for (; row < N; row += stride) {
        float y  = x[row * D + lane];
        // w = mobius_add(-mu, y)
        float xy = warp_sum(-mu_l * y);
        float y2 = warp_sum(y * y);
        float a  = 1.0f + 2.0f * xy;
        float num = (a + y2) * (-mu_l) + omm2 * y;
        float den = fmaxf(a + mu2 * y2, MIN_NORM);
        float w   = num / den;

        // s = mobius_scalar_mul(factor, w)
        float n  = sqrtf(warp_sum(w * w));
        float nc = fminf(fmaxf(n, MIN_NORM), MAX_NORM);
        float t  = tanhf(factor * atanhf(nc));
        float s  = t * (w / nc);
        float s2 = t * t;   // |s|^2 (t is the norm of s by construction)

        // out = mobius_add(onm, s)
        float xs  = warp_sum(onm_l * s);
        float a2  = 1.0f + 2.0f * xs;
        float num2 = (a2 + s2) * onm_l + (1.0f - onm2) * s;
        float den2 = fmaxf(a2 + onm2 * s2, MIN_NORM);
        out[row * D + lane] = num2 / den2;
    }
}

// ---------------------------------------------------------------------------
extern "C" void kernel_launch(void* const* d_in, const int* in_sizes, int n_in,
                              void* d_out, int out_size) {
    const float* x          = (const float*)d_in[0];
    const float* mean_param = (const float*)d_in[1];
    const float* var_param  = (const float*)d_in[2];
    float* out = (float*)d_out;

    const int N = in_sizes[0] / D;

    const int BLOCKS  = 1184;   // 8 blocks/SM on 148 SMs
    const int THREADS = 256;    // 8 warps/block, 1 warp per row

    k_zero<<<1, 33>>>();
    k_pass_log0<<<BLOCKS, THREADS>>>(x, N);
    k_fin_exp0<<<1, 32>>>(N);

    for (int i = 0; i < 10; ++i) {
        k_pass_logmap<<<BLOCKS, THREADS>>>(x, N);
        k_fin_iter<<<1, 32>>>(N);
    }

    k_pass_var<<<BLOCKS, THREADS>>>(x, N);
    k_fin_var<<<1, 32>>>(var_param, mean_param, out, N);

    k_pass_transform<<<BLOCKS, THREADS>>>(x, out, N);
}

// round 2
// speedup vs baseline: 3.5391x; 3.5391x over previous
#include <cuda_runtime.h>

#define D 32
#define EPSF     1e-6f
#define MIN_NORM 1e-15f
#define MAX_NORM (1.0f - 1e-5f)
#define HALF_LN2 0.34657359028f   /* 0.5*ln(2): atanh(n)=HALF_LN2*lg2((1+n)/(1-n)) */
#define LOG2E_X2 2.88539008178f   /* 2*log2(e): tanh(z)=1-2/(exp2(z*LOG2E_X2)+1)  */

// ---------------------------------------------------------------------------
// Persistent device state (no allocations allowed)
__device__ double g_acc[34];            // [0..31] vector acc, [32] scalar acc
__device__ __align__(16) float g_mu[D];
__device__ float  g_mu2;
__device__ __align__(16) float g_onm[D];
__device__ float  g_onm2, g_factor, g_dmuonm;
__device__ float  g_y2[1 << 20];        // per-row squared norms (N <= 1M)

// ---------------------------------------------------------------------------
// Fast MUFU intrinsics (guaranteed approx instructions regardless of flags)
__device__ __forceinline__ float f_rcp(float x)   { float r; asm("rcp.approx.ftz.f32 %0,%1;"   : "=f"(r) : "f"(x)); return r; }
__device__ __forceinline__ float f_rsqrt(float x) { float r; asm("rsqrt.approx.ftz.f32 %0,%1;" : "=f"(r) : "f"(x)); return r; }
__device__ __forceinline__ float f_lg2(float x)   { float r; asm("lg2.approx.ftz.f32 %0,%1;"   : "=f"(r) : "f"(x)); return r; }
__device__ __forceinline__ float f_ex2(float x)   { float r; asm("ex2.approx.ftz.f32 %0,%1;"   : "=f"(r) : "f"(x)); return r; }

__device__ __forceinline__ float warp_sum(float v) {
#pragma unroll
    for (int o = 16; o > 0; o >>= 1) v += __shfl_xor_sync(0xffffffffu, v, o);
    return v;
}
// sum over each consecutive group of 8 lanes
__device__ __forceinline__ float gsum8(float v) {
    v += __shfl_xor_sync(0xffffffffu, v, 1);
    v += __shfl_xor_sync(0xffffffffu, v, 2);
    v += __shfl_xor_sync(0xffffffffu, v, 4);
    return v;
}
__device__ __forceinline__ float dot4(float4 a, float4 b) {
    return a.x * b.x + a.y * b.y + a.z * b.z + a.w * b.w;
}
__device__ __forceinline__ float atanh_fast(float n) {
    return HALF_LN2 * f_lg2((1.0f + n) * f_rcp(1.0f - n));
}

// ---------------------------------------------------------------------------
__global__ void k_zero() {
    int t = threadIdx.x;
    if (t < 34) g_acc[t] = 0.0;
}

// ---------------------------------------------------------------------------
// Pass 1: per-row |y|^2 (stored) + sum of log0(y).  Layout: 8 lanes per row,
// float4 per lane, 4 rows per warp.  lane = rq*8 + cg.
__global__ void __launch_bounds__(256) k_pass_log0(const float4* __restrict__ x4, int N) {
    __shared__ float sacc[32];
    int tid = threadIdx.x, lane = tid & 31, warp = tid >> 5;
    if (tid < 32) sacc[tid] = 0.0f;
    __syncthreads();

    const int cg = lane & 7, rq = lane >> 3;
    float a0 = 0.f, a1 = 0.f, a2 = 0.f, a3 = 0.f;

    long long Q  = ((long long)N + 3) >> 2;
    long long q  = (long long)blockIdx.x * (blockDim.x >> 5) + warp;
    long long qs = (long long)gridDim.x * (blockDim.x >> 5);
    for (; q < Q; q += qs) {
        long long row = q * 4 + rq;
        bool valid = row < (long long)N;
        long long r = valid ? row : 0;
        float4 y = x4[r * 8 + cg];
        float y2 = gsum8(dot4(y, y));
        if (valid && cg == 0) g_y2[r] = y2;

        float y2c = fmaxf(y2, 1e-30f);
        float rs  = f_rsqrt(y2c);
        float n   = y2c * rs;
        float nc  = fminf(n, MAX_NORM);
        float c   = atanh_fast(nc) * f_rcp(nc);
        if (!valid) c = 0.0f;
        a0 += c * y.x; a1 += c * y.y; a2 += c * y.z; a3 += c * y.w;
    }
#pragma unroll
    for (int o = 8; o < 32; o <<= 1) {
        a0 += __shfl_xor_sync(0xffffffffu, a0, o);
        a1 += __shfl_xor_sync(0xffffffffu, a1, o);
        a2 += __shfl_xor_sync(0xffffffffu, a2, o);
        a3 += __shfl_xor_sync(0xffffffffu, a3, o);
    }
    if (rq == 0) {
        atomicAdd(&sacc[cg * 4 + 0], a0);
        atomicAdd(&sacc[cg * 4 + 1], a1);
        atomicAdd(&sacc[cg * 4 + 2], a2);
        atomicAdd(&sacc[cg * 4 + 3], a3);
    }
    __syncthreads();
    if (tid < 32) atomicAdd(&g_acc[tid], (double)sacc[tid]);
}

// mu = exp0(acc / N); zero acc
__global__ void k_fin_exp0(int N) {
    int l = threadIdx.x;   // 32 threads
    float v  = (float)(g_acc[l] / (double)N);
    float n  = fmaxf(sqrtf(warp_sum(v * v)), MIN_NORM);
    float mu = tanhf(n) * (v / n);
    g_mu[l]  = mu;
    float m2 = warp_sum(mu * mu);
    g_acc[l] = 0.0;
    if (l == 0) { g_mu2 = m2; g_acc[32] = 0.0; }
}

// ---------------------------------------------------------------------------
// Frechet iteration pass: acc += log_map(mu, y) decomposed as
//   coef*(-A*mu + B*y),  coef = B*atanh(nc)*inv/nc,  using precomputed |y|^2.
__global__ void __launch_bounds__(256) k_pass_logmap(const float4* __restrict__ x4,
                                                     const float* __restrict__ y2g,
                                                     int N) {
    __shared__ float sacc[32];
    __shared__ float scm;
    int tid = threadIdx.x, lane = tid & 31, warp = tid >> 5;
    if (tid < 32) sacc[tid] = 0.0f;
    if (tid == 0) scm = 0.0f;
    __syncthreads();

    const int cg = lane & 7, rq = lane >> 3;
    const float4 mu  = ((const float4*)g_mu)[cg];
    const float  mu2 = g_mu2;
    const float  B   = 1.0f - mu2;

    float a0 = 0.f, a1 = 0.f, a2 = 0.f, a3 = 0.f, cm = 0.f;

    long long Q  = ((long long)N + 3) >> 2;
    long long q  = (long long)blockIdx.x * (blockDim.x >> 5) + warp;
    long long qs = (long long)gridDim.x * (blockDim.x >> 5);
    for (; q < Q; q += qs) {
        long long row = q * 4 + rq;
        bool valid = row < (long long)N;
        long long r = valid ? row : 0;
        float4 y  = x4[r * 8 + cg];
        float  y2 = y2g[r];

        float d   = gsum8(dot4(mu, y));
        float A   = 1.0f - 2.0f * d + y2;
        float den = fmaxf(1.0f - 2.0f * d + mu2 * y2, MIN_NORM);
        float inv = f_rcp(den);
        float w2  = inv * inv * (A * A * mu2 - 2.0f * A * B * d + B * B * y2);
        w2 = fmaxf(w2, 1e-30f);
        float rs  = f_rsqrt(w2);
        float n   = w2 * rs;
        float nc  = fminf(n, MAX_NORM);
        float invn = f_rcp(nc);
        float coef = B * atanh_fast(nc) * inv * invn;
        if (!valid) coef = 0.0f;
        float cy = coef * B;
        cm += coef * A;
        a0 += cy * y.x; a1 += cy * y.y; a2 += cy * y.z; a3 += cy * y.w;
    }
#pragma unroll
    for (int o = 8; o < 32; o <<= 1) {
        a0 += __shfl_xor_sync(0xffffffffu, a0, o);
        a1 += __shfl_xor_sync(0xffffffffu, a1, o);
        a2 += __shfl_xor_sync(0xffffffffu, a2, o);
        a3 += __shfl_xor_sync(0xffffffffu, a3, o);
        cm += __shfl_xor_sync(0xffffffffu, cm, o);
    }
    if (rq == 0) {
        atomicAdd(&sacc[cg * 4 + 0], a0);
        atomicAdd(&sacc[cg * 4 + 1], a1);
        atomicAdd(&sacc[cg * 4 + 2], a2);
        atomicAdd(&sacc[cg * 4 + 3], a3);
        if (cg == 0) atomicAdd(&scm, cm);
    }
    __syncthreads();
    if (tid < 32) atomicAdd(&g_acc[tid], (double)sacc[tid]);
    if (tid == 0) atomicAdd(&g_acc[32], (double)scm);
}

// mu = exp_map(mu, (accY - Cm*mu)/N); zero acc
__global__ void k_fin_iter(int N) {
    int l = threadIdx.x;   // 32 threads
    float mu  = g_mu[l];
    float mu2 = g_mu2;
    float v   = (float)((g_acc[l] - g_acc[32] * (double)mu) / (double)N);

    float n = fmaxf(sqrtf(warp_sum(v * v)), MIN_NORM);
    float u = tanhf(n / (1.0f - mu2)) * (v / n);

    float xy = warp_sum(mu * u);
    float u2 = warp_sum(u * u);
    float a  = 1.0f + 2.0f * xy;
    float num = (a + u2) * mu + (1.0f - mu2) * u;
    float den = fmaxf(a + mu2 * u2, MIN_NORM);
    float mun = num / den;

    g_mu[l]  = mun;
    float m2 = warp_sum(mun * mun);
    g_acc[l] = 0.0;
    if (l == 0) { g_mu2 = m2; g_acc[32] = 0.0; }
}

// ---------------------------------------------------------------------------
// Variance pass: sum of (2*atanh(|mobius_add(-mu,y)|))^2, analytic |w|^2.
__global__ void __launch_bounds__(256) k_pass_var(const float4* __restrict__ x4,
                                                  const float* __restrict__ y2g,
                                                  int N) {
    __shared__ float ssum;
    int tid = threadIdx.x, lane = tid & 31, warp = tid >> 5;
    if (tid == 0) ssum = 0.0f;
    __syncthreads();

    const int cg = lane & 7, rq = lane >> 3;
    const float4 mu  = ((const float4*)g_mu)[cg];
    const float  mu2 = g_mu2;
    const float  B   = 1.0f - mu2;

    float vacc = 0.0f;
    long long Q  = ((long long)N + 3) >> 2;
    long long q  = (long long)blockIdx.x * (blockDim.x >> 5) + warp;
    long long qs = (long long)gridDim.x * (blockDim.x >> 5);
    for (; q < Q; q += qs) {
        long long row = q * 4 + rq;
        bool valid = row < (long long)N;
        long long r = valid ? row : 0;
        float4 y  = x4[r * 8 + cg];
        float  y2 = y2g[r];

        float d   = gsum8(dot4(mu, y));
        float A   = 1.0f - 2.0f * d + y2;
        float den = fmaxf(1.0f - 2.0f * d + mu2 * y2, MIN_NORM);
        float inv = f_rcp(den);
        float w2  = inv * inv * (A * A * mu2 - 2.0f * A * B * d + B * B * y2);
        w2 = fmaxf(w2, 0.0f);
        float rs = f_rsqrt(fmaxf(w2, 1e-30f));
        float n  = w2 * rs;
        float nc = fminf(n, MAX_NORM);
        float dist = 2.0f * atanh_fast(nc);
        if (valid) vacc += dist * dist;
    }
#pragma unroll
    for (int o = 8; o < 32; o <<= 1) vacc += __shfl_xor_sync(0xffffffffu, vacc, o);
    if (lane == 0) atomicAdd(&ssum, vacc);
    __syncthreads();
    if (tid == 0) atomicAdd(&g_acc[32], (double)ssum);
}

// factor, on_manifold, dot(onm,mu); write input_mean to output tail
__global__ void k_fin_var(const float* __restrict__ var_param,
                          const float* __restrict__ mean_param,
                          float* __restrict__ out, int N) {
    int l = threadIdx.x;   // 32 threads
    float var    = (float)(g_acc[32] / (double)N);
    float factor = var_param[0] / sqrtf(var + EPSF);

    float m   = mean_param[l];
    float n   = fmaxf(sqrtf(warp_sum(m * m)), MIN_NORM);
    float onm = tanhf(n) * (m / n);
    g_onm[l]  = onm;
    float o2  = warp_sum(onm * onm);
    float dmo = warp_sum(onm * g_mu[l]);
    if (l == 0) { g_onm2 = o2; g_factor = factor; g_dmuonm = dmo; g_acc[32] = 0.0; }

    out[(long long)N * D + l] = g_mu[l];
}

// ---------------------------------------------------------------------------
// Final transform: out = mobius_add(onm, mobius_scalar_mul(factor, mobius_add(-mu, y)))
// Everything scalar except two joint 3-step group reductions (d, e).
__global__ void __launch_bounds__(256) k_pass_transform(const float4* __restrict__ x4,
                                                        const float* __restrict__ y2g,
                                                        float4* __restrict__ out4, int N) {
    int tid = threadIdx.x, lane = tid & 31, warp = tid >> 5;
    const int cg = lane & 7, rq = lane >> 3;

    const float4 mu  = ((const float4*)g_mu)[cg];
    const float  mu2 = g_mu2;
    const float  B   = 1.0f - mu2;
    const float4 onm = ((const float4*)g_onm)[cg];
    const float  onm2 = g_onm2;
    const float  fac  = g_factor;
    const float  dmo  = g_dmuonm;

    long long Q  = ((long long)N + 3) >> 2;
    long long q  = (long long)blockIdx.x * (blockDim.x >> 5) + warp;
    long long qs = (long long)gridDim.x * (blockDim.x >> 5);
    for (; q < Q; q += qs) {
        long long row = q * 4 + rq;
        bool valid = row < (long long)N;
        long long r = valid ? row : 0;
        float4 y  = x4[r * 8 + cg];
        float  y2 = y2g[r];

        float d = gsum8(dot4(mu, y));
        float e = gsum8(dot4(onm, y));

        float A   = 1.0f - 2.0f * d + y2;
        float den = fmaxf(1.0f - 2.0f * d + mu2 * y2, MIN_NORM);
        float inv = f_rcp(den);
        float w2  = inv * inv * (A * A * mu2 - 2.0f * A * B * d + B * B * y2);
        w2 = fmaxf(w2, 1e-30f);
        float rs   = f_rsqrt(w2);
        float n    = w2 * rs;
        float nc   = fminf(fmaxf(n, MIN_NORM), MAX_NORM);
        float invn = f_rcp(nc);
        float at   = atanh_fast(nc);

        // t = tanh(fac * at), fac*at >= 0
        float z  = fac * at;
        float ez = f_ex2(z * LOG2E_X2);
        float t  = 1.0f - 2.0f * f_rcp(ez + 1.0f);
        float s2 = t * t;

        float k  = t * invn * inv;     // s_j = k*(-A*mu_j + B*y_j)
        float xs = k * (B * e - A * dmo);

        float a2  = 1.0f + 2.0f * xs;
        float c_on = a2 + s2;          // coefficient of onm
        float c_s  = 1.0f - onm2;      // coefficient of s
        float den2 = fmaxf(a2 + onm2 * s2, MIN_NORM);
        float inv2 = f_rcp(den2);

        float kA = -k * A, kB = k * B; // s = kA*mu + kB*y
        float4 o;
        o.x = inv2 * (c_on * onm.x + c_s * (kA * mu.x + kB * y.x));
        o.y = inv2 * (c_on * onm.y + c_s * (kA * mu.y + kB * y.y));
        o.z = inv2 * (c_on * onm.z + c_s * (kA * mu.z + kB * y.z));
        o.w = inv2 * (c_on * onm.w + c_s * (kA * mu.w + kB * y.w));
        if (valid) out4[r * 8 + cg] = o;
    }
}

// ---------------------------------------------------------------------------
extern "C" void kernel_launch(void* const* d_in, const int* in_sizes, int n_in,
                              void* d_out, int out_size) {
    const float4* x4         = (const float4*)d_in[0];
    const float*  mean_param = (const float*)d_in[1];
    const float*  var_param  = (const float*)d_in[2];
    float*  out  = (float*)d_out;
    float4* out4 = (float4*)d_out;

    const int N = in_sizes[0] / D;

    const int BLOCKS  = 1184;   // ~8 blocks/SM
    const int THREADS = 256;    // 8 warps/block, 4 rows per warp-iter

    // y2g points at the device-global scratch
    float* y2g_host = nullptr;
    cudaGetSymbolAddress((void**)&y2g_host, g_y2);
    const float* y2g = y2g_host;

    k_zero<<<1, 34>>>();
    k_pass_log0<<<BLOCKS, THREADS>>>(x4, N);
    k_fin_exp0<<<1, 32>>>(N);

    for (int i = 0; i < 10; ++i) {
        k_pass_logmap<<<BLOCKS, THREADS>>>(x4, y2g, N);
        k_fin_iter<<<1, 32>>>(N);
    }

    k_pass_var<<<BLOCKS, THREADS>>>(x4, y2g, N);
    k_fin_var<<<1, 32>>>(var_param, mean_param, out, N);

    k_pass_transform<<<BLOCKS, THREADS>>>(x4, y2g, out4, N);
}

// round 3
// speedup vs baseline: 4.1766x; 1.1801x over previous
#include <cuda_runtime.h>

#define D 32
#define EPSF     1e-6f
#define MIN_NORM 1e-15f
#define MAX_NORM (1.0f - 1e-5f)
#define HALF_LN2 0.34657359028f   /* 0.5*ln(2): atanh(n)=HALF_LN2*lg2((1+n)/(1-n)) */
#define LOG2E_X2 2.88539008178f   /* 2*log2(e): tanh(z)=1-2/(exp2(z*LOG2E_X2)+1)  */
#define SKIP_TH  1e-20f           /* |v|^2 threshold: update norm < 1e-10 => frozen */

// ---------------------------------------------------------------------------
// Persistent device state (no allocations allowed)
__device__ double g_acc[34];            // [0..31] vector acc, [32] scalar acc
__device__ __align__(16) float g_mu[D];
__device__ float  g_mu2;
__device__ __align__(16) float g_onm[D];
__device__ float  g_onm2, g_factor, g_dmuonm;
__device__ int    g_skip;               // frechet converged flag
__device__ unsigned g_cnt;              // last-block counter (reset by finalizer)
__device__ float  g_y2[1 << 20];        // per-row squared norms (N <= 1M)

// ---------------------------------------------------------------------------
__device__ __forceinline__ float f_rcp(float x)   { float r; asm("rcp.approx.ftz.f32 %0,%1;"   : "=f"(r) : "f"(x)); return r; }
__device__ __forceinline__ float f_rsqrt(float x) { float r; asm("rsqrt.approx.ftz.f32 %0,%1;" : "=f"(r) : "f"(x)); return r; }
__device__ __forceinline__ float f_lg2(float x)   { float r; asm("lg2.approx.ftz.f32 %0,%1;"   : "=f"(r) : "f"(x)); return r; }
__device__ __forceinline__ float f_ex2(float x)   { float r; asm("ex2.approx.ftz.f32 %0,%1;"   : "=f"(r) : "f"(x)); return r; }

__device__ __forceinline__ float warp_sum(float v) {
#pragma unroll
    for (int o = 16; o > 0; o >>= 1) v += __shfl_xor_sync(0xffffffffu, v, o);
    return v;
}
__device__ __forceinline__ float gsum8(float v) {   // sum within 8-lane groups
    v += __shfl_xor_sync(0xffffffffu, v, 1);
    v += __shfl_xor_sync(0xffffffffu, v, 2);
    v += __shfl_xor_sync(0xffffffffu, v, 4);
    return v;
}
__device__ __forceinline__ float dot4(float4 a, float4 b) {
    return a.x * b.x + a.y * b.y + a.z * b.z + a.w * b.w;
}
__device__ __forceinline__ float atanh_fast(float n) {
    return HALF_LN2 * f_lg2((1.0f + n) * f_rcp(1.0f - n));
}

// Last-block election: returns true in all threads of the last block to arrive.
__device__ __forceinline__ bool last_block_elect(int tid) {
    __shared__ int s_last;
    __threadfence();
    if (tid == 0) {
        unsigned t = atomicAdd(&g_cnt, 1u);
        s_last = (t == gridDim.x - 1u);
    }
    __syncthreads();
    return s_last != 0;
}

// ---------------------------------------------------------------------------
// Pass 1: per-row |y|^2 (stored) + sum of log0(y) + fused finalize (mu = exp0(mean)).
__global__ void __launch_bounds__(256) k_pass_log0(const float4* __restrict__ x4, int N) {
    __shared__ float sacc[32];
    int tid = threadIdx.x, lane = tid & 31, warp = tid >> 5;
    if (tid < 32) sacc[tid] = 0.0f;
    __syncthreads();

    const int cg = lane & 7, rq = lane >> 3;
    float a0 = 0.f, a1 = 0.f, a2 = 0.f, a3 = 0.f;

    long long Q  = ((long long)N + 3) >> 2;
    long long q  = (long long)blockIdx.x * (blockDim.x >> 5) + warp;
    long long qs = (long long)gridDim.x * (blockDim.x >> 5);
#pragma unroll 2
    for (; q < Q; q += qs) {
        long long row = q * 4 + rq;
        bool valid = row < (long long)N;
        long long r = valid ? row : 0;
        float4 y = x4[r * 8 + cg];
        float y2 = gsum8(dot4(y, y));
        if (valid && cg == 0) g_y2[r] = y2;

        float y2c = fmaxf(y2, 1e-30f);
        float rs  = f_rsqrt(y2c);
        float n   = y2c * rs;
        float nc  = fminf(n, MAX_NORM);
        float c   = atanh_fast(nc) * f_rcp(nc);
        if (!valid) c = 0.0f;
        a0 += c * y.x; a1 += c * y.y; a2 += c * y.z; a3 += c * y.w;
    }
#pragma unroll
    for (int o = 8; o < 32; o <<= 1) {
        a0 += __shfl_xor_sync(0xffffffffu, a0, o);
        a1 += __shfl_xor_sync(0xffffffffu, a1, o);
        a2 += __shfl_xor_sync(0xffffffffu, a2, o);
        a3 += __shfl_xor_sync(0xffffffffu, a3, o);
    }
    if (rq == 0) {
        atomicAdd(&sacc[cg * 4 + 0], a0);
        atomicAdd(&sacc[cg * 4 + 1], a1);
        atomicAdd(&sacc[cg * 4 + 2], a2);
        atomicAdd(&sacc[cg * 4 + 3], a3);
    }
    __syncthreads();
    if (tid < 32) atomicAdd(&g_acc[tid], (double)sacc[tid]);

    // -------- fused finalize: mu = exp0(acc / N)
    if (last_block_elect(tid) && tid < 32) {
        int l = tid;
        float v  = (float)(g_acc[l] / (double)N);
        float n  = fmaxf(sqrtf(warp_sum(v * v)), MIN_NORM);
        float mu = tanhf(n) * (v / n);
        g_mu[l]  = mu;
        float m2 = warp_sum(mu * mu);
        g_acc[l] = 0.0;
        if (l == 0) { g_mu2 = m2; g_acc[32] = 0.0; g_skip = 0; g_cnt = 0u; }
    }
}

// ---------------------------------------------------------------------------
// Frechet iteration pass: acc += log_map(mu, y) = coef*(-A*mu + B*y), using
// precomputed |y|^2 and analytic |w|^2. Fused finalize: mu = exp_map(mu, v).
// Early-exits (whole kernel) once updates have converged below SKIP_TH.
__global__ void __launch_bounds__(256) k_pass_logmap(const float4* __restrict__ x4,
                                                     const float* __restrict__ y2g,
                                                     int N) {
    if (g_skip) return;

    __shared__ float sacc[32];
    __shared__ float scm;
    int tid = threadIdx.x, lane = tid & 31, warp = tid >> 5;
    if (tid < 32) sacc[tid] = 0.0f;
    if (tid == 0) scm = 0.0f;
    __syncthreads();

    const int cg = lane & 7, rq = lane >> 3;
    const float4 mu  = ((const float4*)g_mu)[cg];
    const float  mu2 = g_mu2;
    const float  B   = 1.0f - mu2;

    float a0 = 0.f, a1 = 0.f, a2 = 0.f, a3 = 0.f, cm = 0.f;

    long long Q  = ((long long)N + 3) >> 2;
    long long q  = (long long)blockIdx.x * (blockDim.x >> 5) + warp;
    long long qs = (long long)gridDim.x * (blockDim.x >> 5);
#pragma unroll 2
    for (; q < Q; q += qs) {
        long long row = q * 4 + rq;
        bool valid = row < (long long)N;
        long long r = valid ? row : 0;
        float4 y  = x4[r * 8 + cg];
        float  y2 = y2g[r];

        float d   = gsum8(dot4(mu, y));
        float A   = 1.0f - 2.0f * d + y2;
        float den = fmaxf(1.0f - 2.0f * d + mu2 * y2, MIN_NORM);
        float inv = f_rcp(den);
        float w2  = inv * inv * (A * A * mu2 - 2.0f * A * B * d + B * B * y2);
        w2 = fmaxf(w2, 1e-30f);
        float rs  = f_rsqrt(w2);
        float n   = w2 * rs;
        float nc  = fminf(n, MAX_NORM);
        float invn = f_rcp(nc);
        float coef = B * atanh_fast(nc) * inv * invn;
        if (!valid) coef = 0.0f;
        float cy = coef * B;
        cm += coef * A;
        a0 += cy * y.x; a1 += cy * y.y; a2 += cy * y.z; a3 += cy * y.w;
    }
#pragma unroll
    for (int o = 8; o < 32; o <<= 1) {
        a0 += __shfl_xor_sync(0xffffffffu, a0, o);
        a1 += __shfl_xor_sync(0xffffffffu, a1, o);
        a2 += __shfl_xor_sync(0xffffffffu, a2, o);
        a3 += __shfl_xor_sync(0xffffffffu, a3, o);
        cm += __shfl_xor_sync(0xffffffffu, cm, o);
    }
    if (rq == 0) {
        atomicAdd(&sacc[cg * 4 + 0], a0);
        atomicAdd(&sacc[cg * 4 + 1], a1);
        atomicAdd(&sacc[cg * 4 + 2], a2);
        atomicAdd(&sacc[cg * 4 + 3], a3);
        if (cg == 0) atomicAdd(&scm, cm);
    }
    __syncthreads();
    if (tid < 32) atomicAdd(&g_acc[tid], (double)sacc[tid]);
    if (tid == 0) atomicAdd(&g_acc[32], (double)scm);

    // -------- fused finalize: mu = exp_map(mu, (accY - Cm*mu)/N)
    if (last_block_elect(tid) && tid < 32) {
        int l = tid;
        float muv  = g_mu[l];
        float m2o  = g_mu2;
        float v    = (float)((g_acc[l] - g_acc[32] * (double)muv) / (double)N);

        float n2 = warp_sum(v * v);
        float n  = fmaxf(sqrtf(n2), MIN_NORM);
        float u  = tanhf(n / (1.0f - m2o)) * (v / n);

        float xy = warp_sum(muv * u);
        float u2 = warp_sum(u * u);
        float a  = 1.0f + 2.0f * xy;
        float num = (a + u2) * muv + (1.0f - m2o) * u;
        float den = fmaxf(a + m2o * u2, MIN_NORM);
        float mun = num / den;

        g_mu[l]  = mun;
        float m2 = warp_sum(mun * mun);
        g_acc[l] = 0.0;
        if (l == 0) {
            g_mu2 = m2;
            g_acc[32] = 0.0;
            g_cnt = 0u;
            if (n2 < SKIP_TH) g_skip = 1;   // converged: remaining passes no-op
        }
    }
}

// ---------------------------------------------------------------------------
// Variance pass + fused finalize (factor, on_manifold, <onm,mu>, write mean tail).
__global__ void __launch_bounds__(256) k_pass_var(const float4* __restrict__ x4,
                                                  const float* __restrict__ y2g,
                                                  const float* __restrict__ var_param,
                                                  const float* __restrict__ mean_param,
                                                  float* __restrict__ out,
                                                  int N) {
    __shared__ float ssum;
    int tid = threadIdx.x, lane = tid & 31, warp = tid >> 5;
    if (tid == 0) ssum = 0.0f;
    __syncthreads();

    const int cg = lane & 7, rq = lane >> 3;
    const float4 mu  = ((const float4*)g_mu)[cg];
    const float  mu2 = g_mu2;
    const float  B   = 1.0f - mu2;

    float vacc = 0.0f;
    long long Q  = ((long long)N + 3) >> 2;
    long long q  = (long long)blockIdx.x * (blockDim.x >> 5) + warp;
    long long qs = (long long)gridDim.x * (blockDim.x >> 5);
#pragma unroll 2
    for (; q < Q; q += qs) {
        long long row = q * 4 + rq;
        bool valid = row < (long long)N;
        long long r = valid ? row : 0;
        float4 y  = x4[r * 8 + cg];
        float  y2 = y2g[r];

        float d   = gsum8(dot4(mu, y));
        float A   = 1.0f - 2.0f * d + y2;
        float den = fmaxf(1.0f - 2.0f * d + mu2 * y2, MIN_NORM);
        float inv = f_rcp(den);
        float w2  = inv * inv * (A * A * mu2 - 2.0f * A * B * d + B * B * y2);
        w2 = fmaxf(w2, 0.0f);
        float rs = f_rsqrt(fmaxf(w2, 1e-30f));
        float n  = w2 * rs;
        float nc = fminf(n, MAX_NORM);
        float dist = 2.0f * atanh_fast(nc);
        if (valid) vacc += dist * dist;
    }
#pragma unroll
    for (int o = 8; o < 32; o <<= 1) vacc += __shfl_xor_sync(0xffffffffu, vacc, o);
    if (lane == 0) atomicAdd(&ssum, vacc);
    __syncthreads();
    if (tid == 0) atomicAdd(&g_acc[32], (double)ssum);

    // -------- fused finalize
    if (last_block_elect(tid) && tid < 32) {
        int l = tid;
        float var    = (float)(g_acc[32] / (double)N);
        float factor = var_param[0] / sqrtf(var + EPSF);

        float m   = mean_param[l];
        float n   = fmaxf(sqrtf(warp_sum(m * m)), MIN_NORM);
        float onm = tanhf(n) * (m / n);
        g_onm[l]  = onm;
        float o2  = warp_sum(onm * onm);
        float dmo = warp_sum(onm * g_mu[l]);
        if (l == 0) {
            g_onm2 = o2; g_factor = factor; g_dmuonm = dmo;
            g_acc[32] = 0.0; g_cnt = 0u;
        }
        out[(long long)N * D + l] = g_mu[l];   // input_mean tail
    }
}

// ---------------------------------------------------------------------------
// Final transform: out = mobius_add(onm, mobius_scalar_mul(factor, mobius_add(-mu, y)))
__global__ void __launch_bounds__(256) k_pass_transform(const float4* __restrict__ x4,
                                                        const float* __restrict__ y2g,
                                                        float4* __restrict__ out4, int N) {
    int tid = threadIdx.x, lane = tid & 31, warp = tid >> 5;
    const int cg = lane & 7, rq = lane >> 3;

    const float4 mu   = ((const float4*)g_mu)[cg];
    const float  mu2  = g_mu2;
    const float  B    = 1.0f - mu2;
    const float4 onm  = ((const float4*)g_onm)[cg];
    const float  onm2 = g_onm2;
    const float  fac  = g_factor;
    const float  dmo  = g_dmuonm;

    long long Q  = ((long long)N + 3) >> 2;
    long long q  = (long long)blockIdx.x * (blockDim.x >> 5) + warp;
    long long qs = (long long)gridDim.x * (blockDim.x >> 5);
#pragma unroll 2
    for (; q < Q; q += qs) {
        long long row = q * 4 + rq;
        bool valid = row < (long long)N;
        long long r = valid ? row : 0;
        float4 y  = x4[r * 8 + cg];
        float  y2 = y2g[r];

        float d = gsum8(dot4(mu, y));
        float e = gsum8(dot4(onm, y));

        float A   = 1.0f - 2.0f * d + y2;
        float den = fmaxf(1.0f - 2.0f * d + mu2 * y2, MIN_NORM);
        float inv = f_rcp(den);
        float w2  = inv * inv * (A * A * mu2 - 2.0f * A * B * d + B * B * y2);
        w2 = fmaxf(w2, 1e-30f);
        float rs   = f_rsqrt(w2);
        float n    = w2 * rs;
        float nc   = fminf(fmaxf(n, MIN_NORM), MAX_NORM);
        float invn = f_rcp(nc);
        float at   = atanh_fast(nc);

        float z  = fac * at;
        float ez = f_ex2(z * LOG2E_X2);
        float t  = 1.0f - 2.0f * f_rcp(ez + 1.0f);
        float s2 = t * t;

        float k  = t * invn * inv;     // s_j = k*(-A*mu_j + B*y_j)
        float xs = k * (B * e - A * dmo);

        float a2   = 1.0f + 2.0f * xs;
        float c_on = a2 + s2;
        float c_s  = 1.0f - onm2;
        float den2 = fmaxf(a2 + onm2 * s2, MIN_NORM);
        float inv2 = f_rcp(den2);

        float kA = -k * A, kB = k * B;
        float4 o;
        o.x = inv2 * (c_on * onm.x + c_s * (kA * mu.x + kB * y.x));
        o.y = inv2 * (c_on * onm.y + c_s * (kA * mu.y + kB * y.y));
        o.z = inv2 * (c_on * onm.z + c_s * (kA * mu.z + kB * y.z));
        o.w = inv2 * (c_on * onm.w + c_s * (kA * mu.w + kB * y.w));
        if (valid) out4[r * 8 + cg] = o;
    }
}

// ---------------------------------------------------------------------------
extern "C" void kernel_launch(void* const* d_in, const int* in_sizes, int n_in,
                              void* d_out, int out_size) {
    const float4* x4         = (const float4*)d_in[0];
    const float*  mean_param = (const float*)d_in[1];
    const float*  var_param  = (const float*)d_in[2];
    float*  out  = (float*)d_out;
    float4* out4 = (float4*)d_out;

    const int N = in_sizes[0] / D;

    const int BLOCKS  = 1184;
    const int THREADS = 256;

    float* y2g = nullptr;
    cudaGetSymbolAddress((void**)&y2g, g_y2);

    k_pass_log0<<<BLOCKS, THREADS>>>(x4, N);
    for (int i = 0; i < 10; ++i)
        k_pass_logmap<<<BLOCKS, THREADS>>>(x4, y2g, N);
    k_pass_var<<<BLOCKS, THREADS>>>(x4, y2g, var_param, mean_param, out, N);
    k_pass_transform<<<BLOCKS, THREADS>>>(x4, y2g, out4, N);
}

// round 4
// speedup vs baseline: 7.4035x; 1.7726x over previous
#include <cuda_runtime.h>

#define D 32
#define EPSF     1e-6f
#define MIN_NORM 1e-15f
#define MAX_NORM (1.0f - 1e-5f)
#define HALF_LN2 0.34657359028f   /* 0.5*ln(2): atanh(n)=HALF_LN2*(lg2(1+n)-lg2(1-n)) */
#define LOG2E_X2 2.88539008178f   /* 2*log2(e): tanh(z)=1-2/(exp2(z*LOG2E_X2)+1)  */
#define SKIP_TH  1e-12f           /* |v|^2 threshold: |delta mu| < 1e-6 => frozen */

// ---------------------------------------------------------------------------
// Persistent device state (no allocations allowed)
__device__ double g_acc[34];            // [0..31] vector acc, [32] scalar acc
__device__ __align__(16) float g_mu[D];
__device__ float  g_mu2;
__device__ __align__(16) float g_onm[D];
__device__ float  g_onm2, g_factor, g_dmuonm;
__device__ int    g_skip;               // frechet converged flag
__device__ unsigned g_cnt;              // last-block counter (reset by finalizer)
__device__ float  g_y2[1 << 20];        // per-row squared norms (N <= 1M)

// ---------------------------------------------------------------------------
__device__ __forceinline__ float f_rcp(float x)   { float r; asm("rcp.approx.ftz.f32 %0,%1;"   : "=f"(r) : "f"(x)); return r; }
__device__ __forceinline__ float f_rsqrt(float x) { float r; asm("rsqrt.approx.ftz.f32 %0,%1;" : "=f"(r) : "f"(x)); return r; }
__device__ __forceinline__ float f_lg2(float x)   { float r; asm("lg2.approx.ftz.f32 %0,%1;"   : "=f"(r) : "f"(x)); return r; }
__device__ __forceinline__ float f_ex2(float x)   { float r; asm("ex2.approx.ftz.f32 %0,%1;"   : "=f"(r) : "f"(x)); return r; }

__device__ __forceinline__ float warp_sum(float v) {
#pragma unroll
    for (int o = 16; o > 0; o >>= 1) v += __shfl_xor_sync(0xffffffffu, v, o);
    return v;
}
__device__ __forceinline__ float gsum8(float v) {   // sum within 8-lane groups
    v += __shfl_xor_sync(0xffffffffu, v, 1);
    v += __shfl_xor_sync(0xffffffffu, v, 2);
    v += __shfl_xor_sync(0xffffffffu, v, 4);
    return v;
}
__device__ __forceinline__ float dot4(float4 a, float4 b) {
    return a.x * b.x + a.y * b.y + a.z * b.z + a.w * b.w;
}
// atanh with two independent MUFU lg2 (shorter dependency chain than rcp->lg2)
__device__ __forceinline__ float atanh_fast(float n) {
    return HALF_LN2 * (f_lg2(1.0f + n) - f_lg2(1.0f - n));
}

// Last-block election: returns true in all threads of the last block to arrive.
__device__ __forceinline__ bool last_block_elect(int tid) {
    __shared__ int s_last;
    __threadfence();
    if (tid == 0) {
        unsigned t = atomicAdd(&g_cnt, 1u);
        s_last = (t == gridDim.x - 1u);
    }
    __syncthreads();
    return s_last != 0;
}

// ---------------------------------------------------------------------------
// Pass 1: per-row |y|^2 (stored) + sum of log0(y) + fused finalize (mu = exp0(mean)).
__global__ void __launch_bounds__(256) k_pass_log0(const float4* __restrict__ x4, int N) {
    __shared__ float sacc[32];
    int tid = threadIdx.x, lane = tid & 31, warp = tid >> 5;
    if (tid < 32) sacc[tid] = 0.0f;
    __syncthreads();

    const int cg = lane & 7, rq = lane >> 3;
    float a0 = 0.f, a1 = 0.f, a2 = 0.f, a3 = 0.f;

    const int Q  = (N + 3) >> 2;
    int q  = blockIdx.x * (blockDim.x >> 5) + warp;
    const int qs = gridDim.x * (blockDim.x >> 5);
#pragma unroll 4
    for (; q < Q; q += qs) {
        int row = q * 4 + rq;
        bool valid = row < N;
        int r = valid ? row : 0;
        float4 y = x4[r * 8 + cg];
        float y2 = gsum8(dot4(y, y));
        if (valid && cg == 0) g_y2[r] = y2;

        float y2c = fmaxf(y2, 1e-30f);
        float rs  = f_rsqrt(y2c);
        float n   = y2c * rs;
        float nc  = fminf(n, MAX_NORM);
        float c   = atanh_fast(nc) * rs;     // rs == 1/n (n never clamps for interior pts)
        if (!valid) c = 0.0f;
        a0 += c * y.x; a1 += c * y.y; a2 += c * y.z; a3 += c * y.w;
    }
#pragma unroll
    for (int o = 8; o < 32; o <<= 1) {
        a0 += __shfl_xor_sync(0xffffffffu, a0, o);
        a1 += __shfl_xor_sync(0xffffffffu, a1, o);
        a2 += __shfl_xor_sync(0xffffffffu, a2, o);
        a3 += __shfl_xor_sync(0xffffffffu, a3, o);
    }
    if (rq == 0) {
        atomicAdd(&sacc[cg * 4 + 0], a0);
        atomicAdd(&sacc[cg * 4 + 1], a1);
        atomicAdd(&sacc[cg * 4 + 2], a2);
        atomicAdd(&sacc[cg * 4 + 3], a3);
    }
    __syncthreads();
    if (tid < 32) atomicAdd(&g_acc[tid], (double)sacc[tid]);

    // -------- fused finalize: mu = exp0(acc / N)
    if (last_block_elect(tid) && tid < 32) {
        int l = tid;
        float v  = (float)(g_acc[l] / (double)N);
        float n  = fmaxf(sqrtf(warp_sum(v * v)), MIN_NORM);
        float mu = tanhf(n) * (v / n);
        g_mu[l]  = mu;
        float m2 = warp_sum(mu * mu);
        g_acc[l] = 0.0;
        if (l == 0) { g_mu2 = m2; g_acc[32] = 0.0; g_skip = 0; g_cnt = 0u; }
    }
}

// ---------------------------------------------------------------------------
// Frechet iteration pass: acc += log_map(mu, y) = coef*(-A*mu + B*y), using
// precomputed |y|^2 and analytic |w|^2. Fused finalize: mu = exp_map(mu, v).
// Early-exits (whole kernel) once updates have converged below SKIP_TH.
__global__ void __launch_bounds__(256) k_pass_logmap(const float4* __restrict__ x4,
                                                     const float* __restrict__ y2g,
                                                     int N) {
    if (g_skip) return;

    __shared__ float sacc[32];
    __shared__ float scm;
    int tid = threadIdx.x, lane = tid & 31, warp = tid >> 5;
    if (tid < 32) sacc[tid] = 0.0f;
    if (tid == 0) scm = 0.0f;
    __syncthreads();

    const int cg = lane & 7, rq = lane >> 3;
    const float4 mu  = ((const float4*)g_mu)[cg];
    const float  mu2 = g_mu2;
    const float  B   = 1.0f - mu2;

    float a0 = 0.f, a1 = 0.f, a2 = 0.f, a3 = 0.f, cm = 0.f;

    const int Q  = (N + 3) >> 2;
    int q  = blockIdx.x * (blockDim.x >> 5) + warp;
    const int qs = gridDim.x * (blockDim.x >> 5);
#pragma unroll 4
    for (; q < Q; q += qs) {
        int row = q * 4 + rq;
        bool valid = row < N;
        int r = valid ? row : 0;
        float4 y  = x4[r * 8 + cg];
        float  y2 = y2g[r];

        float d   = gsum8(dot4(mu, y));
        float A   = 1.0f - 2.0f * d + y2;
        float den = fmaxf(1.0f - 2.0f * d + mu2 * y2, MIN_NORM);
        float inv = f_rcp(den);
        float w2  = inv * inv * (A * A * mu2 - 2.0f * A * B * d + B * B * y2);
        w2 = fmaxf(w2, 1e-30f);
        float rs  = f_rsqrt(w2);
        float n   = w2 * rs;
        float nc  = fminf(n, MAX_NORM);
        float coef = B * atanh_fast(nc) * inv * rs;   // rs == 1/n
        if (!valid) coef = 0.0f;
        float cy = coef * B;
        cm += coef * A;
        a0 += cy * y.x; a1 += cy * y.y; a2 += cy * y.z; a3 += cy * y.w;
    }
#pragma unroll
    for (int o = 8; o < 32; o <<= 1) {
        a0 += __shfl_xor_sync(0xffffffffu, a0, o);
        a1 += __shfl_xor_sync(0xffffffffu, a1, o);
        a2 += __shfl_xor_sync(0xffffffffu, a2, o);
        a3 += __shfl_xor_sync(0xffffffffu, a3, o);
        cm += __shfl_xor_sync(0xffffffffu, cm, o);
    }
    if (rq == 0) {
        atomicAdd(&sacc[cg * 4 + 0], a0);
        atomicAdd(&sacc[cg * 4 + 1], a1);
        atomicAdd(&sacc[cg * 4 + 2], a2);
        atomicAdd(&sacc[cg * 4 + 3], a3);
        if (cg == 0) atomicAdd(&scm, cm);
    }
    __syncthreads();
    if (tid < 32) atomicAdd(&g_acc[tid], (double)sacc[tid]);
    if (tid == 0) atomicAdd(&g_acc[32], (double)scm);

    // -------- fused finalize: mu = exp_map(mu, (accY - Cm*mu)/N)
    if (last_block_elect(tid) && tid < 32) {
        int l = tid;
        float muv  = g_mu[l];
        float m2o  = g_mu2;
        float v    = (float)((g_acc[l] - g_acc[32] * (double)muv) / (double)N);

        float n2 = warp_sum(v * v);
        float n  = fmaxf(sqrtf(n2), MIN_NORM);
        float u  = tanhf(n / (1.0f - m2o)) * (v / n);

        float xy = warp_sum(muv * u);
        float u2 = warp_sum(u * u);
        float a  = 1.0f + 2.0f * xy;
        float num = (a + u2) * muv + (1.0f - m2o) * u;
        float den = fmaxf(a + m2o * u2, MIN_NORM);
        float mun = num / den;

        g_mu[l]  = mun;
        float m2 = warp_sum(mun * mun);
        g_acc[l] = 0.0;
        if (l == 0) {
            g_mu2 = m2;
            g_acc[32] = 0.0;
            g_cnt = 0u;
            if (n2 < SKIP_TH) g_skip = 1;   // converged: remaining passes no-op
        }
    }
}

// ---------------------------------------------------------------------------
// Variance pass + fused finalize (factor, on_manifold, <onm,mu>, write mean tail).
__global__ void __launch_bounds__(256) k_pass_var(const float4* __restrict__ x4,
                                                  const float* __restrict__ y2g,
                                                  const float* __restrict__ var_param,
                                                  const float* __restrict__ mean_param,
                                                  float* __restrict__ out,
                                                  int N) {
    __shared__ float ssum;
    int tid = threadIdx.x, lane = tid & 31, warp = tid >> 5;
    if (tid == 0) ssum = 0.0f;
    __syncthreads();

    const int cg = lane & 7, rq = lane >> 3;
    const float4 mu  = ((const float4*)g_mu)[cg];
    const float  mu2 = g_mu2;
    const float  B   = 1.0f - mu2;

    float vacc = 0.0f;
    const int Q  = (N + 3) >> 2;
    int q  = blockIdx.x * (blockDim.x >> 5) + warp;
    const int qs = gridDim.x * (blockDim.x >> 5);
#pragma unroll 4
    for (; q < Q; q += qs) {
        int row = q * 4 + rq;
        bool valid = row < N;
        int r = valid ? row : 0;
        float4 y  = x4[r * 8 + cg];
        float  y2 = y2g[r];

        float d   = gsum8(dot4(mu, y));
        float A   = 1.0f - 2.0f * d + y2;
        float den = fmaxf(1.0f - 2.0f * d + mu2 * y2, MIN_NORM);
        float inv = f_rcp(den);
        float w2  = inv * inv * (A * A * mu2 - 2.0f * A * B * d + B * B * y2);
        w2 = fmaxf(w2, 0.0f);
        float rs = f_rsqrt(fmaxf(w2, 1e-30f));
        float n  = w2 * rs;
        float nc = fminf(n, MAX_NORM);
        float dist = 2.0f * atanh_fast(nc);
        if (valid) vacc += dist * dist;
    }
#pragma unroll
    for (int o = 8; o < 32; o <<= 1) vacc += __shfl_xor_sync(0xffffffffu, vacc, o);
    if (lane == 0) atomicAdd(&ssum, vacc);
    __syncthreads();
    if (tid == 0) atomicAdd(&g_acc[32], (double)ssum);

    // -------- fused finalize
    if (last_block_elect(tid) && tid < 32) {
        int l = tid;
        float var    = (float)(g_acc[32] / (double)N);
        float factor = var_param[0] / sqrtf(var + EPSF);

        float m   = mean_param[l];
        float n   = fmaxf(sqrtf(warp_sum(m * m)), MIN_NORM);
        float onm = tanhf(n) * (m / n);
        g_onm[l]  = onm;
        float o2  = warp_sum(onm * onm);
        float dmo = warp_sum(onm * g_mu[l]);
        if (l == 0) {
            g_onm2 = o2; g_factor = factor; g_dmuonm = dmo;
            g_acc[32] = 0.0; g_cnt = 0u;
        }
        out[N * D + l] = g_mu[l];   // input_mean tail
    }
}

// ---------------------------------------------------------------------------
// Final transform: out = mobius_add(onm, mobius_scalar_mul(factor, mobius_add(-mu, y)))
__global__ void __launch_bounds__(256) k_pass_transform(const float4* __restrict__ x4,
                                                        const float* __restrict__ y2g,
                                                        float4* __restrict__ out4, int N) {
    int tid = threadIdx.x, lane = tid & 31, warp = tid >> 5;
    const int cg = lane & 7, rq = lane >> 3;

    const float4 mu   = ((const float4*)g_mu)[cg];
    const float  mu2  = g_mu2;
    const float  B    = 1.0f - mu2;
    const float4 onm  = ((const float4*)g_onm)[cg];
    const float  onm2 = g_onm2;
    const float  fac  = g_factor;
    const float  dmo  = g_dmuonm;

    const int Q  = (N + 3) >> 2;
    int q  = blockIdx.x * (blockDim.x >> 5) + warp;
    const int qs = gridDim.x * (blockDim.x >> 5);
#pragma unroll 4
    for (; q < Q; q += qs) {
        int row = q * 4 + rq;
        bool valid = row < N;
        int r = valid ? row : 0;
        float4 y  = x4[r * 8 + cg];
        float  y2 = y2g[r];

        float d = gsum8(dot4(mu, y));
        float e = gsum8(dot4(onm, y));

        float A   = 1.0f - 2.0f * d + y2;
        float den = fmaxf(1.0f - 2.0f * d + mu2 * y2, MIN_NORM);
        float inv = f_rcp(den);
        float w2  = inv * inv * (A * A * mu2 - 2.0f * A * B * d + B * B * y2);
        w2 = fmaxf(w2, 1e-30f);
        float rs   = f_rsqrt(w2);
        float n    = w2 * rs;
        float nc   = fminf(fmaxf(n, MIN_NORM), MAX_NORM);
        float at   = atanh_fast(nc);

        float z  = fac * at;
        float ez = f_ex2(z * LOG2E_X2);
        float t  = 1.0f - 2.0f * f_rcp(ez + 1.0f);
        float s2 = t * t;

        float k  = t * rs * inv;       // rs == 1/|w|; s_j = k*(-A*mu_j + B*y_j)
        float xs = k * (B * e - A * dmo);

        float a2   = 1.0f + 2.0f * xs;
        float c_on = a2 + s2;
        float c_s  = 1.0f - onm2;
        float den2 = fmaxf(a2 + onm2 * s2, MIN_NORM);
        float inv2 = f_rcp(den2);

        float kA = -k * A, kB = k * B;
        float4 o;
        o.x = inv2 * (c_on * onm.x + c_s * (kA * mu.x + kB * y.x));
        o.y = inv2 * (c_on * onm.y + c_s * (kA * mu.y + kB * y.y));
        o.z = inv2 * (c_on * onm.z + c_s * (kA * mu.z + kB * y.z));
        o.w = inv2 * (c_on * onm.w + c_s * (kA * mu.w + kB * y.w));
        if (valid) out4[r * 8 + cg] = o;
    }
}

// ---------------------------------------------------------------------------
extern "C" void kernel_launch(void* const* d_in, const int* in_sizes, int n_in,
                              void* d_out, int out_size) {
    const float4* x4         = (const float4*)d_in[0];
    const float*  mean_param = (const float*)d_in[1];
    const float*  var_param  = (const float*)d_in[2];
    float*  out  = (float*)d_out;
    float4* out4 = (float4*)d_out;

    const int N = in_sizes[0] / D;

    const int BLOCKS  = 888;    // 148 SMs * 6 blocks (40 regs/thread) = one full wave
    const int THREADS = 256;

    float* y2g = nullptr;
    cudaGetSymbolAddress((void**)&y2g, g_y2);

    k_pass_log0<<<BLOCKS, THREADS>>>(x4, N);
    for (int i = 0; i < 10; ++i)
        k_pass_logmap<<<BLOCKS, THREADS>>>(x4, y2g, N);
    k_pass_var<<<BLOCKS, THREADS>>>(x4, y2g, var_param, mean_param, out, N);
    k_pass_transform<<<BLOCKS, THREADS>>>(x4, y2g, out4, N);
}

// round 5
// speedup vs baseline: 7.6577x; 1.0343x over previous
#include <cuda_runtime.h>

#define D 32
#define EPSF     1e-6f
#define MIN_NORM 1e-15f
#define MAX_NORM (1.0f - 1e-5f)
#define HALF_LN2 0.34657359028f   /* 0.5*ln(2): atanh(n)=HALF_LN2*(lg2(1+n)-lg2(1-n)) */
#define LOG2E_X2 2.88539008178f   /* 2*log2(e): tanh(z)=1-2/(exp2(z*LOG2E_X2)+1)  */
#define SKIP_TH  1e-12f           /* |v|^2 threshold: |delta mu| < 1e-6 => frozen */

// ---------------------------------------------------------------------------
// Persistent device state (no allocations allowed)
__device__ double g_acc[34];            // [0..31] vector acc, [32] Cm acc, [33] var acc
__device__ __align__(16) float g_mu[D];
__device__ float  g_mu2;
__device__ float  g_var;                // latest variance estimate
__device__ int    g_skip;               // frechet converged flag
__device__ unsigned g_cnt;              // last-block counter (reset by finalizer)
__device__ float  g_y2[1 << 20];        // per-row squared norms (N <= 1M)

// ---------------------------------------------------------------------------
__device__ __forceinline__ float f_rcp(float x)   { float r; asm("rcp.approx.ftz.f32 %0,%1;"   : "=f"(r) : "f"(x)); return r; }
__device__ __forceinline__ float f_rsqrt(float x) { float r; asm("rsqrt.approx.ftz.f32 %0,%1;" : "=f"(r) : "f"(x)); return r; }
__device__ __forceinline__ float f_lg2(float x)   { float r; asm("lg2.approx.ftz.f32 %0,%1;"   : "=f"(r) : "f"(x)); return r; }
__device__ __forceinline__ float f_ex2(float x)   { float r; asm("ex2.approx.ftz.f32 %0,%1;"   : "=f"(r) : "f"(x)); return r; }

__device__ __forceinline__ float warp_sum(float v) {
#pragma unroll
    for (int o = 16; o > 0; o >>= 1) v += __shfl_xor_sync(0xffffffffu, v, o);
    return v;
}
__device__ __forceinline__ float gsum8(float v) {   // sum within 8-lane groups
    v += __shfl_xor_sync(0xffffffffu, v, 1);
    v += __shfl_xor_sync(0xffffffffu, v, 2);
    v += __shfl_xor_sync(0xffffffffu, v, 4);
    return v;
}
__device__ __forceinline__ float dot4(float4 a, float4 b) {
    return a.x * b.x + a.y * b.y + a.z * b.z + a.w * b.w;
}
// atanh with two independent MUFU lg2 (short dependency chain)
__device__ __forceinline__ float atanh_fast(float n) {
    return HALF_LN2 * (f_lg2(1.0f + n) - f_lg2(1.0f - n));
}

// Last-block election: true in all threads of the last block to arrive.
__device__ __forceinline__ bool last_block_elect(int tid) {
    __shared__ int s_last;
    __threadfence();
    if (tid == 0) {
        unsigned t = atomicAdd(&g_cnt, 1u);
        s_last = (t == gridDim.x - 1u);
    }
    __syncthreads();
    return s_last != 0;
}

// ---------------------------------------------------------------------------
// Pass 1: per-row |y|^2 (stored) + sum of log0(y) + fused finalize (mu = exp0(mean)).
__global__ void __launch_bounds__(256, 8) k_pass_log0(const float4* __restrict__ x4, int N) {
    __shared__ float sacc[32];
    int tid = threadIdx.x, lane = tid & 31, warp = tid >> 5;
    if (tid < 32) sacc[tid] = 0.0f;
    __syncthreads();

    const int cg = lane & 7, rq = lane >> 3;
    float a0 = 0.f, a1 = 0.f, a2 = 0.f, a3 = 0.f;

    const int Q  = (N + 3) >> 2;
    int q  = blockIdx.x * (blockDim.x >> 5) + warp;
    const int qs = gridDim.x * (blockDim.x >> 5);
#pragma unroll 4
    for (; q < Q; q += qs) {
        int row = q * 4 + rq;
        bool valid = row < N;
        int r = valid ? row : 0;
        float4 y = x4[r * 8 + cg];
        float y2 = gsum8(dot4(y, y));
        if (valid && cg == 0) g_y2[r] = y2;

        float y2c = fmaxf(y2, 1e-30f);
        float rs  = f_rsqrt(y2c);
        float n   = y2c * rs;
        float nc  = fminf(n, MAX_NORM);
        float c   = atanh_fast(nc) * rs;     // rs == 1/n
        if (!valid) c = 0.0f;
        a0 += c * y.x; a1 += c * y.y; a2 += c * y.z; a3 += c * y.w;
    }
#pragma unroll
    for (int o = 8; o < 32; o <<= 1) {
        a0 += __shfl_xor_sync(0xffffffffu, a0, o);
        a1 += __shfl_xor_sync(0xffffffffu, a1, o);
        a2 += __shfl_xor_sync(0xffffffffu, a2, o);
        a3 += __shfl_xor_sync(0xffffffffu, a3, o);
    }
    if (rq == 0) {
        atomicAdd(&sacc[cg * 4 + 0], a0);
        atomicAdd(&sacc[cg * 4 + 1], a1);
        atomicAdd(&sacc[cg * 4 + 2], a2);
        atomicAdd(&sacc[cg * 4 + 3], a3);
    }
    __syncthreads();
    if (tid < 32) atomicAdd(&g_acc[tid], (double)sacc[tid]);

    // -------- fused finalize: mu = exp0(acc / N)
    if (last_block_elect(tid) && tid < 32) {
        int l = tid;
        float v  = (float)(g_acc[l] / (double)N);
        float n  = fmaxf(sqrtf(warp_sum(v * v)), MIN_NORM);
        float mu = tanhf(n) * (v / n);
        g_mu[l]  = mu;
        float m2 = warp_sum(mu * mu);
        g_acc[l] = 0.0;
        if (l == 0) { g_mu2 = m2; g_acc[32] = 0.0; g_acc[33] = 0.0; g_skip = 0; g_cnt = 0u; }
    }
}

// ---------------------------------------------------------------------------
// Frechet iteration pass: acc += log_map(mu, y) = coef*(-A*mu + B*y), plus
// variance accumulation (4*atanh^2) for the CURRENT mu. Fused finalize updates
// mu and stores g_var. Whole kernel no-ops once converged (g_skip).
__global__ void __launch_bounds__(256, 8) k_pass_logmap(const float4* __restrict__ x4,
                                                        const float* __restrict__ y2g,
                                                        int N) {
    if (g_skip) return;

    __shared__ float sacc[32];
    __shared__ float scm, svar;
    int tid = threadIdx.x, lane = tid & 31, warp = tid >> 5;
    if (tid < 32) sacc[tid] = 0.0f;
    if (tid == 0) { scm = 0.0f; svar = 0.0f; }
    __syncthreads();

    const int cg = lane & 7, rq = lane >> 3;
    const float4 mu  = ((const float4*)g_mu)[cg];
    const float  mu2 = g_mu2;
    const float  B   = 1.0f - mu2;

    float a0 = 0.f, a1 = 0.f, a2 = 0.f, a3 = 0.f, cm = 0.f, va = 0.f;

    const int Q  = (N + 3) >> 2;
    int q  = blockIdx.x * (blockDim.x >> 5) + warp;
    const int qs = gridDim.x * (blockDim.x >> 5);
#pragma unroll 4
    for (; q < Q; q += qs) {
        int row = q * 4 + rq;
        bool valid = row < N;
        int r = valid ? row : 0;
        float4 y  = x4[r * 8 + cg];
        float  y2 = y2g[r];

        float d   = gsum8(dot4(mu, y));
        float A   = 1.0f - 2.0f * d + y2;
        float den = fmaxf(1.0f - 2.0f * d + mu2 * y2, MIN_NORM);
        float inv = f_rcp(den);
        float w2  = inv * inv * (A * A * mu2 - 2.0f * A * B * d + B * B * y2);
        w2 = fmaxf(w2, 1e-30f);
        float rs  = f_rsqrt(w2);
        float n   = w2 * rs;
        float nc  = fminf(n, MAX_NORM);
        float at  = atanh_fast(nc);
        float coef = B * at * inv * rs;   // rs == 1/n
        if (!valid) coef = 0.0f;
        va += valid ? 4.0f * at * at : 0.0f;
        float cy = coef * B;
        cm += coef * A;
        a0 += cy * y.x; a1 += cy * y.y; a2 += cy * y.z; a3 += cy * y.w;
    }
#pragma unroll
    for (int o = 8; o < 32; o <<= 1) {
        a0 += __shfl_xor_sync(0xffffffffu, a0, o);
        a1 += __shfl_xor_sync(0xffffffffu, a1, o);
        a2 += __shfl_xor_sync(0xffffffffu, a2, o);
        a3 += __shfl_xor_sync(0xffffffffu, a3, o);
        cm += __shfl_xor_sync(0xffffffffu, cm, o);
        va += __shfl_xor_sync(0xffffffffu, va, o);
    }
    if (rq == 0) {
        atomicAdd(&sacc[cg * 4 + 0], a0);
        atomicAdd(&sacc[cg * 4 + 1], a1);
        atomicAdd(&sacc[cg * 4 + 2], a2);
        atomicAdd(&sacc[cg * 4 + 3], a3);
        if (cg == 0) { atomicAdd(&scm, cm); atomicAdd(&svar, va); }
    }
    __syncthreads();
    if (tid < 32) atomicAdd(&g_acc[tid], (double)sacc[tid]);
    if (tid == 0) { atomicAdd(&g_acc[32], (double)scm); atomicAdd(&g_acc[33], (double)svar); }

    // -------- fused finalize: mu = exp_map(mu, (accY - Cm*mu)/N); g_var update
    if (last_block_elect(tid) && tid < 32) {
        int l = tid;
        float muv  = g_mu[l];
        float m2o  = g_mu2;
        float v    = (float)((g_acc[l] - g_acc[32] * (double)muv) / (double)N);

        float n2 = warp_sum(v * v);
        float n  = fmaxf(sqrtf(n2), MIN_NORM);
        float u  = tanhf(n / (1.0f - m2o)) * (v / n);

        float xy = warp_sum(muv * u);
        float u2 = warp_sum(u * u);
        float a  = 1.0f + 2.0f * xy;
        float num = (a + u2) * muv + (1.0f - m2o) * u;
        float den = fmaxf(a + m2o * u2, MIN_NORM);
        float mun = num / den;

        g_mu[l]  = mun;
        float m2 = warp_sum(mun * mun);
        g_acc[l] = 0.0;
        if (l == 0) {
            g_mu2 = m2;
            g_var = (float)(g_acc[33] / (double)N);
            g_acc[32] = 0.0;
            g_acc[33] = 0.0;
            g_cnt = 0u;
            if (n2 < SKIP_TH) g_skip = 1;   // converged: remaining passes no-op
        }
    }
}

// ---------------------------------------------------------------------------
// Final transform: out = mobius_add(onm, mobius_scalar_mul(factor, mobius_add(-mu, y)))
// Per-block prologue derives factor/onm/<onm,mu> (cheap, redundant per block).
__global__ void __launch_bounds__(256) k_pass_transform(const float4* __restrict__ x4,
                                                        const float* __restrict__ y2g,
                                                        const float* __restrict__ var_param,
                                                        const float* __restrict__ mean_param,
                                                        float4* __restrict__ out4,
                                                        float* __restrict__ out,
                                                        int N) {
    __shared__ __align__(16) float s_onm[32];
    __shared__ float s_fac, s_onm2, s_dmo;
    int tid = threadIdx.x, lane = tid & 31, warp = tid >> 5;
    const int cg = lane & 7, rq = lane >> 3;

    if (tid < 32) {
        float var    = g_var;
        float factor = var_param[0] / sqrtf(var + EPSF);
        float m   = mean_param[tid];
        float n   = fmaxf(sqrtf(warp_sum(m * m)), MIN_NORM);
        float onm = tanhf(n) * (m / n);
        s_onm[tid] = onm;
        float o2  = warp_sum(onm * onm);
        float dmo = warp_sum(onm * g_mu[tid]);
        if (tid == 0) { s_fac = factor; s_onm2 = o2; s_dmo = dmo; }
        if (blockIdx.x == 0) out[N * D + tid] = g_mu[tid];   // input_mean tail
    }
    __syncthreads();

    const float4 mu   = ((const float4*)g_mu)[cg];
    const float  mu2  = g_mu2;
    const float  B    = 1.0f - mu2;
    const float4 onm  = ((const float4*)s_onm)[cg];
    const float  onm2 = s_onm2;
    const float  fac  = s_fac;
    const float  dmo  = s_dmo;

    const int Q  = (N + 3) >> 2;
    int q  = blockIdx.x * (blockDim.x >> 5) + warp;
    const int qs = gridDim.x * (blockDim.x >> 5);
#pragma unroll 4
    for (; q < Q; q += qs) {
        int row = q * 4 + rq;
        bool valid = row < N;
        int r = valid ? row : 0;
        float4 y  = x4[r * 8 + cg];
        float  y2 = y2g[r];

        float d = gsum8(dot4(mu, y));
        float e = gsum8(dot4(onm, y));

        float A   = 1.0f - 2.0f * d + y2;
        float den = fmaxf(1.0f - 2.0f * d + mu2 * y2, MIN_NORM);
        float inv = f_rcp(den);
        float w2  = inv * inv * (A * A * mu2 - 2.0f * A * B * d + B * B * y2);
        w2 = fmaxf(w2, 1e-30f);
        float rs   = f_rsqrt(w2);
        float n    = w2 * rs;
        float nc   = fminf(fmaxf(n, MIN_NORM), MAX_NORM);
        float at   = atanh_fast(nc);

        float z  = fac * at;
        float ez = f_ex2(z * LOG2E_X2);
        float t  = 1.0f - 2.0f * f_rcp(ez + 1.0f);
        float s2 = t * t;

        float k  = t * rs * inv;       // rs == 1/|w|; s_j = k*(-A*mu_j + B*y_j)
        float xs = k * (B * e - A * dmo);

        float a2   = 1.0f + 2.0f * xs;
        float c_on = a2 + s2;
        float c_s  = 1.0f - onm2;
        float den2 = fmaxf(a2 + onm2 * s2, MIN_NORM);
        float inv2 = f_rcp(den2);

        float kA = -k * A, kB = k * B;
        float4 o;
        o.x = inv2 * (c_on * onm.x + c_s * (kA * mu.x + kB * y.x));
        o.y = inv2 * (c_on * onm.y + c_s * (kA * mu.y + kB * y.y));
        o.z = inv2 * (c_on * onm.z + c_s * (kA * mu.z + kB * y.z));
        o.w = inv2 * (c_on * onm.w + c_s * (kA * mu.w + kB * y.w));
        if (valid) out4[r * 8 + cg] = o;
    }
}

// ---------------------------------------------------------------------------
extern "C" void kernel_launch(void* const* d_in, const int* in_sizes, int n_in,
                              void* d_out, int out_size) {
    const float4* x4         = (const float4*)d_in[0];
    const float*  mean_param = (const float*)d_in[1];
    const float*  var_param  = (const float*)d_in[2];
    float*  out  = (float*)d_out;
    float4* out4 = (float4*)d_out;

    const int N = in_sizes[0] / D;

    const int RBLOCKS = 1184;   // 8 blocks/SM (forced 32 regs) = 100% occupancy
    const int TBLOCKS = 888;    // transform ~40 regs -> 6 blocks/SM, one wave
    const int THREADS = 256;

    float* y2g = nullptr;
    cudaGetSymbolAddress((void**)&y2g, g_y2);

    k_pass_log0<<<RBLOCKS, THREADS>>>(x4, N);
    for (int i = 0; i < 10; ++i)
        k_pass_logmap<<<RBLOCKS, THREADS>>>(x4, y2g, N);
    k_pass_transform<<<TBLOCKS, THREADS>>>(x4, y2g, var_param, mean_param, out4, out, N);
}

// round 6
// speedup vs baseline: 8.6507x; 1.1297x over previous
#include <cuda_runtime.h>

#define D 32
#define EPSF     1e-6f
#define MIN_NORM 1e-15f
#define MAX_NORM (1.0f - 1e-5f)
#define HALF_LN2 0.34657359028f   /* 0.5*ln(2): atanh(n)=HALF_LN2*(lg2(1+n)-lg2(1-n)) */
#define LOG2E_X2 2.88539008178f   /* 2*log2(e): tanh(z)=1-2/(exp2(z*LOG2E_X2)+1)  */
#define SKIP_TH  1e-12f           /* |v|^2 threshold: |delta mu| < 1e-6 => frozen */

// ---------------------------------------------------------------------------
// Persistent device state (no allocations allowed)
__device__ double g_acc[34];            // [0..31] vector acc, [32] Cm acc, [33] var acc
__device__ __align__(16) float g_mu[D];
__device__ float  g_mu2;
__device__ float  g_var;                // latest variance estimate
__device__ int    g_skip;               // frechet converged flag
__device__ unsigned g_cnt;              // last-block counter (reset by finalizer)
__device__ float  g_y2[1 << 20];        // per-row squared norms (N <= 1M)

// ---------------------------------------------------------------------------
__device__ __forceinline__ float f_rcp(float x)   { float r; asm("rcp.approx.ftz.f32 %0,%1;"   : "=f"(r) : "f"(x)); return r; }
__device__ __forceinline__ float f_rsqrt(float x) { float r; asm("rsqrt.approx.ftz.f32 %0,%1;" : "=f"(r) : "f"(x)); return r; }
__device__ __forceinline__ float f_lg2(float x)   { float r; asm("lg2.approx.ftz.f32 %0,%1;"   : "=f"(r) : "f"(x)); return r; }
__device__ __forceinline__ float f_ex2(float x)   { float r; asm("ex2.approx.ftz.f32 %0,%1;"   : "=f"(r) : "f"(x)); return r; }

__device__ __forceinline__ float warp_sum(float v) {
#pragma unroll
    for (int o = 16; o > 0; o >>= 1) v += __shfl_xor_sync(0xffffffffu, v, o);
    return v;
}
__device__ __forceinline__ float gsum8(float v) {   // sum within 8-lane groups
    v += __shfl_xor_sync(0xffffffffu, v, 1);
    v += __shfl_xor_sync(0xffffffffu, v, 2);
    v += __shfl_xor_sync(0xffffffffu, v, 4);
    return v;
}
__device__ __forceinline__ float dot4(float4 a, float4 b) {
    return a.x * b.x + a.y * b.y + a.z * b.z + a.w * b.w;
}
// atanh with two independent MUFU lg2 (short dependency chain)
__device__ __forceinline__ float atanh_fast(float n) {
    return HALF_LN2 * (f_lg2(1.0f + n) - f_lg2(1.0f - n));
}

// Last-block election: true in all threads of the last block to arrive.
__device__ __forceinline__ bool last_block_elect(int tid) {
    __shared__ int s_last;
    __threadfence();
    if (tid == 0) {
        unsigned t = atomicAdd(&g_cnt, 1u);
        s_last = (t == gridDim.x - 1u);
    }
    __syncthreads();
    return s_last != 0;
}

// ---------------------------------------------------------------------------
// Pass 1: per-row |y|^2 (stored) + sum of log0(y) + fused finalize (mu = exp0(mean)).
// Software-pipelined: next iteration's loads issue before current compute.
__global__ void __launch_bounds__(256) k_pass_log0(const float4* __restrict__ x4, int N) {
    __shared__ float sacc[32];
    int tid = threadIdx.x, lane = tid & 31, warp = tid >> 5;
    if (tid < 32) sacc[tid] = 0.0f;
    __syncthreads();

    const int cg = lane & 7, rq = lane >> 3;
    float a0 = 0.f, a1 = 0.f, a2 = 0.f, a3 = 0.f;

    const int Q  = (N + 3) >> 2;
    int q  = blockIdx.x * (blockDim.x >> 5) + warp;
    const int qs = gridDim.x * (blockDim.x >> 5);

    float4 yA; float rA_store; int rA; bool vA;
    {
        int row = q * 4 + rq;
        vA = (q < Q) && (row < N);
        rA = vA ? row : 0;
        yA = x4[rA * 8 + cg];
        rA_store = 0.0f; (void)rA_store;
    }
    for (; q < Q; ) {
        int qn = q + qs;
        float4 yB; int rB; bool vB;
        {
            int row = qn * 4 + rq;
            vB = (qn < Q) && (row < N);
            rB = vB ? row : 0;
            yB = x4[rB * 8 + cg];
        }
        // ---- compute on stage A
        float y2 = gsum8(dot4(yA, yA));
        if (vA && cg == 0) g_y2[rA] = y2;
        float y2c = fmaxf(y2, 1e-30f);
        float rs  = f_rsqrt(y2c);
        float n   = y2c * rs;
        float nc  = fminf(n, MAX_NORM);
        float c   = atanh_fast(nc) * rs;     // rs == 1/n
        if (!vA) c = 0.0f;
        a0 += c * yA.x; a1 += c * yA.y; a2 += c * yA.z; a3 += c * yA.w;

        q = qn; yA = yB; rA = rB; vA = vB;
    }
#pragma unroll
    for (int o = 8; o < 32; o <<= 1) {
        a0 += __shfl_xor_sync(0xffffffffu, a0, o);
        a1 += __shfl_xor_sync(0xffffffffu, a1, o);
        a2 += __shfl_xor_sync(0xffffffffu, a2, o);
        a3 += __shfl_xor_sync(0xffffffffu, a3, o);
    }
    if (rq == 0) {
        atomicAdd(&sacc[cg * 4 + 0], a0);
        atomicAdd(&sacc[cg * 4 + 1], a1);
        atomicAdd(&sacc[cg * 4 + 2], a2);
        atomicAdd(&sacc[cg * 4 + 3], a3);
    }
    __syncthreads();
    if (tid < 32) atomicAdd(&g_acc[tid], (double)sacc[tid]);

    // -------- fused finalize: mu = exp0(acc / N)
    if (last_block_elect(tid) && tid < 32) {
        int l = tid;
        float v  = (float)(g_acc[l] / (double)N);
        float n  = fmaxf(sqrtf(warp_sum(v * v)), MIN_NORM);
        float mu = tanhf(n) * (v / n);
        g_mu[l]  = mu;
        float m2 = warp_sum(mu * mu);
        g_acc[l] = 0.0;
        if (l == 0) { g_mu2 = m2; g_acc[32] = 0.0; g_acc[33] = 0.0; g_skip = 0; g_cnt = 0u; }
    }
}

// ---------------------------------------------------------------------------
// Frechet iteration pass: acc += log_map(mu, y) = coef*(-A*mu + B*y), plus
// variance accumulation (4*atanh^2) for the CURRENT mu. Fused finalize updates
// mu and stores g_var. Whole kernel no-ops once converged (g_skip).
__global__ void __launch_bounds__(256) k_pass_logmap(const float4* __restrict__ x4,
                                                     const float* __restrict__ y2g,
                                                     int N) {
    if (g_skip) return;

    __shared__ float sacc[32];
    __shared__ float scm, svar;
    int tid = threadIdx.x, lane = tid & 31, warp = tid >> 5;
    if (tid < 32) sacc[tid] = 0.0f;
    if (tid == 0) { scm = 0.0f; svar = 0.0f; }
    __syncthreads();

    const int cg = lane & 7, rq = lane >> 3;
    const float4 mu  = ((const float4*)g_mu)[cg];
    const float  mu2 = g_mu2;
    const float  B   = 1.0f - mu2;
    const float  B2  = B * B;

    float a0 = 0.f, a1 = 0.f, a2 = 0.f, a3 = 0.f, cm = 0.f, va = 0.f;

    const int Q  = (N + 3) >> 2;
    int q  = blockIdx.x * (blockDim.x >> 5) + warp;
    const int qs = gridDim.x * (blockDim.x >> 5);

    float4 yA; float y2A; bool vA;
    {
        int row = q * 4 + rq;
        vA = (q < Q) && (row < N);
        int r = vA ? row : 0;
        yA = x4[r * 8 + cg];
        y2A = y2g[r];
    }
    for (; q < Q; ) {
        int qn = q + qs;
        float4 yB; float y2B; bool vB;
        {
            int row = qn * 4 + rq;
            vB = (qn < Q) && (row < N);
            int r = vB ? row : 0;
            yB = x4[r * 8 + cg];
            y2B = y2g[r];
        }
        // ---- compute on stage A
        float d   = gsum8(dot4(mu, yA));
        float den = fmaxf(fmaf(mu2, y2A, 1.0f - 2.0f * d), MIN_NORM);
        float A   = den + B * y2A;            // == 1 - 2d + y2
        float inv = f_rcp(den);
        float P   = fmaf(A, fmaf(A, mu2, -2.0f * B * d), B2 * y2A);
        float w2  = fmaxf(inv * inv * P, 1e-30f);
        float rs  = f_rsqrt(w2);
        float n   = w2 * rs;
        float nc  = fminf(n, MAX_NORM);
        float at  = atanh_fast(nc);
        float coef = B * at * inv * rs;       // rs == 1/n
        if (!vA) coef = 0.0f;
        va += vA ? 4.0f * at * at : 0.0f;
        float cy = coef * B;
        cm = fmaf(coef, A, cm);
        a0 = fmaf(cy, yA.x, a0); a1 = fmaf(cy, yA.y, a1);
        a2 = fmaf(cy, yA.z, a2); a3 = fmaf(cy, yA.w, a3);

        q = qn; yA = yB; y2A = y2B; vA = vB;
    }
#pragma unroll
    for (int o = 8; o < 32; o <<= 1) {
        a0 += __shfl_xor_sync(0xffffffffu, a0, o);
        a1 += __shfl_xor_sync(0xffffffffu, a1, o);
        a2 += __shfl_xor_sync(0xffffffffu, a2, o);
        a3 += __shfl_xor_sync(0xffffffffu, a3, o);
        cm += __shfl_xor_sync(0xffffffffu, cm, o);
        va += __shfl_xor_sync(0xffffffffu, va, o);
    }
    if (rq == 0) {
        atomicAdd(&sacc[cg * 4 + 0], a0);
        atomicAdd(&sacc[cg * 4 + 1], a1);
        atomicAdd(&sacc[cg * 4 + 2], a2);
        atomicAdd(&sacc[cg * 4 + 3], a3);
        if (cg == 0) { atomicAdd(&scm, cm); atomicAdd(&svar, va); }
    }
    __syncthreads();
    if (tid < 32) atomicAdd(&g_acc[tid], (double)sacc[tid]);
    if (tid == 0) { atomicAdd(&g_acc[32], (double)scm); atomicAdd(&g_acc[33], (double)svar); }

    // -------- fused finalize: mu = exp_map(mu, (accY - Cm*mu)/N); g_var update
    if (last_block_elect(tid) && tid < 32) {
        int l = tid;
        float muv  = g_mu[l];
        float m2o  = g_mu2;
        float v    = (float)((g_acc[l] - g_acc[32] * (double)muv) / (double)N);

        float n2 = warp_sum(v * v);
        float n  = fmaxf(sqrtf(n2), MIN_NORM);
        float u  = tanhf(n / (1.0f - m2o)) * (v / n);

        float xy = warp_sum(muv * u);
        float u2 = warp_sum(u * u);
        float a  = 1.0f + 2.0f * xy;
        float num = (a + u2) * muv + (1.0f - m2o) * u;
        float den = fmaxf(a + m2o * u2, MIN_NORM);
        float mun = num / den;

        g_mu[l]  = mun;
        float m2 = warp_sum(mun * mun);
        g_acc[l] = 0.0;
        if (l == 0) {
            g_mu2 = m2;
            g_var = (float)(g_acc[33] / (double)N);
            g_acc[32] = 0.0;
            g_acc[33] = 0.0;
            g_cnt = 0u;
            if (n2 < SKIP_TH) g_skip = 1;   // converged: remaining passes no-op
        }
    }
}

// ---------------------------------------------------------------------------
// Final transform: out = mobius_add(onm, mobius_scalar_mul(factor, mobius_add(-mu, y)))
// Per-block prologue derives factor/onm/<onm,mu> (cheap, redundant per block).
__global__ void __launch_bounds__(256) k_pass_transform(const float4* __restrict__ x4,
                                                        const float* __restrict__ y2g,
                                                        const float* __restrict__ var_param,
                                                        const float* __restrict__ mean_param,
                                                        float4* __restrict__ out4,
                                                        float* __restrict__ out,
                                                        int N) {
    __shared__ __align__(16) float s_onm[32];
    __shared__ float s_fac, s_onm2, s_dmo;
    int tid = threadIdx.x, lane = tid & 31, warp = tid >> 5;
    const int cg = lane & 7, rq = lane >> 3;

    if (tid < 32) {
        float var    = g_var;
        float factor = var_param[0] / sqrtf(var + EPSF);
        float m   = mean_param[tid];
        float n   = fmaxf(sqrtf(warp_sum(m * m)), MIN_NORM);
        float onm = tanhf(n) * (m / n);
        s_onm[tid] = onm;
        float o2  = warp_sum(onm * onm);
        float dmo = warp_sum(onm * g_mu[tid]);
        if (tid == 0) { s_fac = factor; s_onm2 = o2; s_dmo = dmo; }
        if (blockIdx.x == 0) out[N * D + tid] = g_mu[tid];   // input_mean tail
    }
    __syncthreads();

    const float4 mu   = ((const float4*)g_mu)[cg];
    const float  mu2  = g_mu2;
    const float  B    = 1.0f - mu2;
    const float  B2   = B * B;
    const float4 onm  = ((const float4*)s_onm)[cg];
    const float  onm2 = s_onm2;
    const float  fac  = s_fac;
    const float  dmo  = s_dmo;

    const int Q  = (N + 3) >> 2;
    int q  = blockIdx.x * (blockDim.x >> 5) + warp;
    const int qs = gridDim.x * (blockDim.x >> 5);

    float4 yA; float y2A; int rA; bool vA;
    {
        int row = q * 4 + rq;
        vA = (q < Q) && (row < N);
        rA = vA ? row : 0;
        yA = x4[rA * 8 + cg];
        y2A = y2g[rA];
    }
    for (; q < Q; ) {
        int qn = q + qs;
        float4 yB; float y2B; int rB; bool vB;
        {
            int row = qn * 4 + rq;
            vB = (qn < Q) && (row < N);
            rB = vB ? row : 0;
            yB = x4[rB * 8 + cg];
            y2B = y2g[rB];
        }
        // ---- compute on stage A
        float d = gsum8(dot4(mu, yA));
        float e = gsum8(dot4(onm, yA));

        float den = fmaxf(fmaf(mu2, y2A, 1.0f - 2.0f * d), MIN_NORM);
        float A   = den + B * y2A;
        float inv = f_rcp(den);
        float P   = fmaf(A, fmaf(A, mu2, -2.0f * B * d), B2 * y2A);
        float w2  = fmaxf(inv * inv * P, 1e-30f);
        float rs   = f_rsqrt(w2);
        float n    = w2 * rs;
        float nc   = fminf(fmaxf(n, MIN_NORM), MAX_NORM);
        float at   = atanh_fast(nc);

        float z  = fac * at;
        float ez = f_ex2(z * LOG2E_X2);
        float t  = 1.0f - 2.0f * f_rcp(ez + 1.0f);
        float s2 = t * t;

        float k  = t * rs * inv;       // rs == 1/|w|; s_j = k*(-A*mu_j + B*y_j)
        float xs = k * (B * e - A * dmo);

        float a2   = 1.0f + 2.0f * xs;
        float c_on = a2 + s2;
        float c_s  = 1.0f - onm2;
        float den2 = fmaxf(a2 + onm2 * s2, MIN_NORM);
        float inv2 = f_rcp(den2);

        float kA = -k * A, kB = k * B;
        float4 o;
        o.x = inv2 * (c_on * onm.x + c_s * (kA * mu.x + kB * yA.x));
        o.y = inv2 * (c_on * onm.y + c_s * (kA * mu.y + kB * yA.y));
        o.z = inv2 * (c_on * onm.z + c_s * (kA * mu.z + kB * yA.z));
        o.w = inv2 * (c_on * onm.w + c_s * (kA * mu.w + kB * yA.w));
        if (vA) out4[rA * 8 + cg] = o;

        q = qn; yA = yB; y2A = y2B; rA = rB; vA = vB;
    }
}

// ---------------------------------------------------------------------------
extern "C" void kernel_launch(void* const* d_in, const int* in_sizes, int n_in,
                              void* d_out, int out_size) {
    const float4* x4         = (const float4*)d_in[0];
    const float*  mean_param = (const float*)d_in[1];
    const float*  var_param  = (const float*)d_in[2];
    float*  out  = (float*)d_out;
    float4* out4 = (float4*)d_out;

    const int N = in_sizes[0] / D;

    const int BLOCKS  = 888;    // ~6 blocks/SM at ~40 regs, one full wave
    const int THREADS = 256;
    const int SMALL   = 148;    // late (normally converged/no-op) passes

    float* y2g = nullptr;
    cudaGetSymbolAddress((void**)&y2g, g_y2);

    k_pass_log0<<<BLOCKS, THREADS>>>(x4, N);
    for (int i = 0; i < 4; ++i)
        k_pass_logmap<<<BLOCKS, THREADS>>>(x4, y2g, N);
    for (int i = 4; i < 10; ++i)
        k_pass_logmap<<<SMALL, THREADS>>>(x4, y2g, N);
    k_pass_transform<<<BLOCKS, THREADS>>>(x4, y2g, var_param, mean_param, out4, out, N);
}